// round 15
// baseline (speedup 1.0000x reference)
#include <cuda_runtime.h>

#define S_LEN 2048
#define DM    512
#define NH    8
#define BATCH 4
#define NORMED_ELEMS (BATCH*S_LEN*DM)
#define ATTN_SMEM 46848

// -------- scratch --------
__device__ float g_Qp[BATCH*S_LEN*DM];
__device__ float g_Kp[BATCH*S_LEN*DM];
__device__ float g_Vp[BATCH*S_LEN*DM];
__device__ float g_ctx[BATCH*S_LEN*DM];
__device__ float g_rowsum[BATCH*NH*S_LEN];
__device__ int   g_mask_mode;   // 0=int32, 1=uint8/bool, 2=float32

// -------- helpers --------
__device__ __forceinline__ unsigned f2tf(float x){
    unsigned u; asm("cvt.rna.tf32.f32 %0, %1;" : "=r"(u) : "f"(x)); return u;
}
__device__ __forceinline__ float f2tff(float x){ return __uint_as_float(f2tf(x)); }

__device__ __forceinline__ void mma_tf32(float c[4],
    unsigned a0, unsigned a1, unsigned a2, unsigned a3, unsigned b0, unsigned b1)
{
    asm volatile(
      "mma.sync.aligned.m16n8k8.row.col.f32.tf32.tf32.f32 "
      "{%0,%1,%2,%3}, {%4,%5,%6,%7}, {%8,%9}, {%0,%1,%2,%3};"
      : "+f"(c[0]), "+f"(c[1]), "+f"(c[2]), "+f"(c[3])
      : "r"(a0), "r"(a1), "r"(a2), "r"(a3), "r"(b0), "r"(b1));
}

// -------- mask dtype probe --------
__global__ void detect_mask_kernel(const unsigned char* __restrict__ m)
{
    __shared__ int s_gt1, s_off;
    if (threadIdx.x == 0){ s_gt1 = 0; s_off = 0; }
    __syncthreads();
    int gt1 = 0, off = 0;
    for (int i = threadIdx.x; i < 8192; i += 256){
        unsigned char v = m[i];
        if (v > 1) gt1 = 1;
        if ((i & 3) && v) off = 1;
    }
    if (gt1) atomicOr(&s_gt1, 1);
    if (off) atomicOr(&s_off, 1);
    __syncthreads();
    if (threadIdx.x == 0) g_mask_mode = s_gt1 ? 2 : (s_off ? 1 : 0);
}

// -------- GEMM with register-prefetch pipeline --------
// round_out=1: store tf32-rounded outputs (Q/K/V projections) so the attention
// loader's cvt becomes unnecessary (idempotent -> removed; bit-identical).
__global__ void __launch_bounds__(128, 4) gemm_kernel(
    const float* __restrict__ A, const float* __restrict__ W,
    const float* __restrict__ resid, float* __restrict__ C, int round_out)
{
    __shared__ float As[64*36], Ws[64*36];
    const int tid = threadIdx.x, lane = tid & 31, w = tid >> 5;
    const int m0 = blockIdx.x * 64, n0 = blockIdx.y * 64;

    float acc[8][4];
    #pragma unroll
    for (int i = 0; i < 8; i++){ acc[i][0]=0.f; acc[i][1]=0.f; acc[i][2]=0.f; acc[i][3]=0.f; }

    float4 af[4], wf[4];
    #pragma unroll
    for (int i = 0; i < 4; i++){
        int f = tid + i*128, r = f >> 3, fc = (f & 7)*4;
        af[i] = *reinterpret_cast<const float4*>(A + (size_t)(m0+r)*512 + fc);
        wf[i] = *reinterpret_cast<const float4*>(W + (size_t)(n0+r)*512 + fc);
    }

    for (int k0 = 0; k0 < 512; k0 += 32){
        __syncthreads();
        #pragma unroll
        for (int i = 0; i < 4; i++){
            int f = tid + i*128, r = f >> 3, fc = (f & 7)*4;
            As[r*36+fc  ]=f2tff(af[i].x); As[r*36+fc+1]=f2tff(af[i].y);
            As[r*36+fc+2]=f2tff(af[i].z); As[r*36+fc+3]=f2tff(af[i].w);
            Ws[r*36+fc  ]=f2tff(wf[i].x); Ws[r*36+fc+1]=f2tff(wf[i].y);
            Ws[r*36+fc+2]=f2tff(wf[i].z); Ws[r*36+fc+3]=f2tff(wf[i].w);
        }
        if (k0 + 32 < 512){
            #pragma unroll
            for (int i = 0; i < 4; i++){
                int f = tid + i*128, r = f >> 3, fc = (f & 7)*4;
                af[i] = *reinterpret_cast<const float4*>(A + (size_t)(m0+r)*512 + k0+32 + fc);
                wf[i] = *reinterpret_cast<const float4*>(W + (size_t)(n0+r)*512 + k0+32 + fc);
            }
        }
        __syncthreads();
        const int ar = w*16 + (lane >> 2);
        #pragma unroll
        for (int ks = 0; ks < 4; ks++){
            int kk = ks*8 + (lane & 3);
            unsigned a0=__float_as_uint(As[ar*36+kk]),   a1=__float_as_uint(As[(ar+8)*36+kk]);
            unsigned a2=__float_as_uint(As[ar*36+kk+4]), a3=__float_as_uint(As[(ar+8)*36+kk+4]);
            #pragma unroll
            for (int nt = 0; nt < 8; nt++){
                int br = nt*8 + (lane >> 2);
                unsigned b0=__float_as_uint(Ws[br*36+kk]), b1=__float_as_uint(Ws[br*36+kk+4]);
                mma_tf32(acc[nt], a0,a1,a2,a3, b0,b1);
            }
        }
    }

    const int r0 = m0 + w*16 + (lane >> 2);
    const int r1 = r0 + 8;
    #pragma unroll
    for (int nt = 0; nt < 8; nt++){
        int c = n0 + nt*8 + (lane & 3)*2;
        float2 v0 = make_float2(acc[nt][0], acc[nt][1]);
        float2 v1 = make_float2(acc[nt][2], acc[nt][3]);
        if (resid){
            float2 rlo = *reinterpret_cast<const float2*>(resid + (size_t)r0*512 + c);
            float2 rhi = *reinterpret_cast<const float2*>(resid + (size_t)r1*512 + c);
            v0.x += rlo.x; v0.y += rlo.y; v1.x += rhi.x; v1.y += rhi.y;
        }
        if (round_out){
            v0.x = f2tff(v0.x); v0.y = f2tff(v0.y);
            v1.x = f2tff(v1.x); v1.y = f2tff(v1.y);
        }
        *reinterpret_cast<float2*>(C + (size_t)r0*512 + c) = v0;
        *reinterpret_cast<float2*>(C + (size_t)r1*512 + c) = v1;
    }
}

// -------- attention (R9 layout; loaders cvt-free + vectorized STS) --------
// grid (32, NH, B), 128 threads; q-tile 64, kv-tile 32. Inputs are tf32-pre-
// rounded by the projection gemm, so loads store raw bits (bit-identical).
__global__ void __launch_bounds__(128, 4) attn_kernel(
    const void* __restrict__ maskp, float* __restrict__ attn_out)
{
    extern __shared__ float sm[];
    float* Qs  = sm;            // 64*68
    float* Ks  = Qs + 64*68;    // 32*68
    float* Vst = Ks + 32*68;    // [64 d][32 kv] stride 36
    float* Es  = Vst + 64*36;   // [64 q][32 kv] stride 36
    float* ls  = Es + 64*36;    // 64 rowsums
    unsigned char* Ms = (unsigned char*)(ls + 64); // 64*32

    const int tid = threadIdx.x, lane = tid & 31, w = tid >> 5;
    const int b = blockIdx.z, h = blockIdx.y, q0 = blockIdx.x * 64;
    const int mode = g_mask_mode;
    const unsigned char* m8  = (const unsigned char*)maskp;
    const int*           m32 = (const int*)maskp;
    const float*         mf  = (const float*)maskp;
    const size_t mbase = (size_t)b * S_LEN * S_LEN;

    // Q tile (reshape-bug row mapping), raw vector copy (pre-rounded)
    {
        int r = tid >> 1, hc = (tid & 1) * 32;
        int sq = q0 + r;
        const float* qrow = g_Qp + ((size_t)(b*S_LEN) + h*256 + (sq>>3))*512 + (sq&7)*64;
        #pragma unroll
        for (int i = 0; i < 8; i++){
            *reinterpret_cast<float4*>(Qs + r*68 + hc + i*4) =
                *reinterpret_cast<const float4*>(qrow + hc + i*4);
        }
    }
    if (tid < 64) ls[tid] = 0.f;

    float cacc[8][4];
    #pragma unroll
    for (int i = 0; i < 8; i++){ cacc[i][0]=0.f; cacc[i][1]=0.f; cacc[i][2]=0.f; cacc[i][3]=0.f; }

    const int rlo = w*16 + (lane >> 2);
    const int rhi = rlo + 8;

    const int lr = tid >> 2, lqo = (tid & 3) * 16;   // kv row / d-col for K,V
    const int mr = tid >> 1, moff = (tid & 1) * 16;  // mask row / col

    float4 kf[4], vf[4];
    uint4  mreg;
    // prefetch tile 0
    {
        size_t rowoff = ((size_t)(b*S_LEN) + h*256 + (lr>>3))*512 + (lr&7)*64 + lqo;
        #pragma unroll
        for (int i = 0; i < 4; i++){
            kf[i] = *reinterpret_cast<const float4*>(g_Kp + rowoff + i*4);
            vf[i] = *reinterpret_cast<const float4*>(g_Vp + rowoff + i*4);
        }
        if (mode == 1)
            mreg = *reinterpret_cast<const uint4*>(m8 + mbase + (size_t)(q0+mr)*S_LEN + moff);
    }

    for (int kt = 0; kt < 64; ++kt){
        const int k0 = kt * 32;
        __syncthreads();   // previous tile fully consumed
        // ---- store prefetched K (STS.128) + V transposed (scalar, no cvt) ----
        #pragma unroll
        for (int i = 0; i < 4; i++){
            int qo = lqo + i*4;
            *reinterpret_cast<float4*>(Ks + lr*68 + qo) = kf[i];
            Vst[(qo  )*36 + lr] = vf[i].x;
            Vst[(qo+1)*36 + lr] = vf[i].y;
            Vst[(qo+2)*36 + lr] = vf[i].z;
            Vst[(qo+3)*36 + lr] = vf[i].w;
        }
        // ---- mask store ----
        if (mode == 1){
            *reinterpret_cast<uint4*>(Ms + mr*32 + moff) = mreg;
        } else {
            size_t mrow = mbase + (size_t)(q0 + mr) * S_LEN + k0 + moff;
            if (mode == 0){
                #pragma unroll 4
                for (int c = 0; c < 16; c++) Ms[mr*32+moff+c] = (unsigned char)(m32[mrow+c] != 0);
            } else {
                #pragma unroll 4
                for (int c = 0; c < 16; c++) Ms[mr*32+moff+c] = (unsigned char)(mf[mrow+c] != 0.f);
            }
        }
        // ---- prefetch next tile (overlaps compute below) ----
        if (kt + 1 < 64){
            int skv = k0 + 32 + lr;
            size_t rowoff = ((size_t)(b*S_LEN) + h*256 + (skv>>3))*512 + (skv&7)*64 + lqo;
            #pragma unroll
            for (int i = 0; i < 4; i++){
                kf[i] = *reinterpret_cast<const float4*>(g_Kp + rowoff + i*4);
                vf[i] = *reinterpret_cast<const float4*>(g_Vp + rowoff + i*4);
            }
            if (mode == 1)
                mreg = *reinterpret_cast<const uint4*>(m8 + mbase + (size_t)(q0+mr)*S_LEN + k0+32 + moff);
        }
        __syncthreads();

        // ---- scores = Q @ K^T ----
        float sc[4][4];
        #pragma unroll
        for (int i = 0; i < 4; i++){ sc[i][0]=0.f; sc[i][1]=0.f; sc[i][2]=0.f; sc[i][3]=0.f; }
        #pragma unroll
        for (int ks = 0; ks < 8; ks++){
            int kk = ks*8 + (lane & 3);
            unsigned a0=__float_as_uint(Qs[rlo*68+kk]),   a1=__float_as_uint(Qs[rhi*68+kk]);
            unsigned a2=__float_as_uint(Qs[rlo*68+kk+4]), a3=__float_as_uint(Qs[rhi*68+kk+4]);
            #pragma unroll
            for (int nt = 0; nt < 4; nt++){
                int br = nt*8 + (lane >> 2);
                unsigned b0=__float_as_uint(Ks[br*68+kk]), b1=__float_as_uint(Ks[br*68+kk+4]);
                mma_tf32(sc[nt], a0,a1,a2,a3, b0,b1);
            }
        }
        // ---- mask + exp + rowsums ----
        float plo = 0.f, phi = 0.f;
        #pragma unroll
        for (int nt = 0; nt < 4; nt++){
            int c = nt*8 + (lane & 3)*2;
            float p0 = Ms[rlo*32 + c  ] ? 0.f : __expf(sc[nt][0]*0.125f);
            float p1 = Ms[rlo*32 + c+1] ? 0.f : __expf(sc[nt][1]*0.125f);
            float p2 = Ms[rhi*32 + c  ] ? 0.f : __expf(sc[nt][2]*0.125f);
            float p3 = Ms[rhi*32 + c+1] ? 0.f : __expf(sc[nt][3]*0.125f);
            Es[rlo*36 + c] = p0; Es[rlo*36 + c+1] = p1;
            Es[rhi*36 + c] = p2; Es[rhi*36 + c+1] = p3;
            plo += p0 + p1; phi += p2 + p3;
        }
        plo += __shfl_xor_sync(0xffffffffu, plo, 1);
        plo += __shfl_xor_sync(0xffffffffu, plo, 2);
        phi += __shfl_xor_sync(0xffffffffu, phi, 1);
        phi += __shfl_xor_sync(0xffffffffu, phi, 2);
        if ((lane & 3) == 0){ ls[rlo] += plo; ls[rhi] += phi; }
        __syncwarp();

        // ---- write unnormalized probs (warp-owned rows) ----
        {
            float* arow = attn_out + ((size_t)(b*NH + h)*S_LEN + q0)*S_LEN + k0;
            #pragma unroll
            for (int ps = 0; ps < 4; ps++){
                int r  = w*16 + ps*4 + (lane >> 3);
                int cc = (lane & 7) * 4;
                float4 v;
                v.x = Es[r*36+cc]; v.y = Es[r*36+cc+1]; v.z = Es[r*36+cc+2]; v.w = Es[r*36+cc+3];
                *reinterpret_cast<float4*>(arow + (size_t)r*S_LEN + cc) = v;
            }
        }
        // ---- context += E @ V ----
        #pragma unroll
        for (int ks = 0; ks < 4; ks++){
            int kk = ks*8 + (lane & 3);
            unsigned a0 = f2tf(Es[rlo*36 + kk]);
            unsigned a1 = f2tf(Es[rhi*36 + kk]);
            unsigned a2 = f2tf(Es[rlo*36 + kk + 4]);
            unsigned a3 = f2tf(Es[rhi*36 + kk + 4]);
            #pragma unroll
            for (int nt = 0; nt < 8; nt++){
                int br = nt*8 + (lane >> 2);
                unsigned b0 = __float_as_uint(Vst[br*36+kk]), b1 = __float_as_uint(Vst[br*36+kk+4]);
                mma_tf32(cacc[nt], a0,a1,a2,a3, b0,b1);
            }
        }
    }
    __syncthreads();

    // normalized context -> g_ctx (b, s, h*64+d)
    const float il0 = 1.0f / ls[rlo];
    const float il1 = 1.0f / ls[rhi];
    float* c0p = g_ctx + ((size_t)(b*S_LEN) + q0 + rlo)*512 + h*64;
    float* c1p = g_ctx + ((size_t)(b*S_LEN) + q0 + rhi)*512 + h*64;
    #pragma unroll
    for (int nt = 0; nt < 8; nt++){
        int c = nt*8 + (lane & 3)*2;
        *reinterpret_cast<float2*>(c0p + c) = make_float2(cacc[nt][0]*il0, cacc[nt][1]*il0);
        *reinterpret_cast<float2*>(c1p + c) = make_float2(cacc[nt][2]*il1, cacc[nt][3]*il1);
    }
    if (tid < 64) g_rowsum[(size_t)(b*NH + h)*S_LEN + q0 + tid] = ls[tid];
}

// -------- rescale attn rows by 1/rowsum (streaming RMW) --------
__global__ void __launch_bounds__(256) attn_scale_kernel(float* __restrict__ attn)
{
    size_t row = blockIdx.x;
    float inv = 1.0f / g_rowsum[row];
    float* p = attn + row * S_LEN;
    int t = threadIdx.x;
    #pragma unroll
    for (int i = 0; i < 2; i++){
        float4 v = *reinterpret_cast<float4*>(p + t*4 + i*1024);
        v.x *= inv; v.y *= inv; v.z *= inv; v.w *= inv;
        *reinterpret_cast<float4*>(p + t*4 + i*1024) = v;
    }
}

// -------- LayerNorm --------
__global__ void __launch_bounds__(128) ln_kernel(
    const float* __restrict__ x, const float* __restrict__ gamma,
    const float* __restrict__ beta, float* __restrict__ out)
{
    __shared__ float rs[4], rq[4];
    int row = blockIdx.x, tid = threadIdx.x;
    const float* xr = x + (size_t)row * 512;
    float4 v = *reinterpret_cast<const float4*>(xr + tid*4);
    float s = v.x + v.y + v.z + v.w;
    float q = v.x*v.x + v.y*v.y + v.z*v.z + v.w*v.w;
    #pragma unroll
    for (int o = 16; o; o >>= 1){
        s += __shfl_xor_sync(0xffffffffu, s, o);
        q += __shfl_xor_sync(0xffffffffu, q, o);
    }
    if ((tid & 31) == 0){ rs[tid>>5] = s; rq[tid>>5] = q; }
    __syncthreads();
    s = rs[0]+rs[1]+rs[2]+rs[3];
    q = rq[0]+rq[1]+rq[2]+rq[3];
    float mean = s * (1.0f/512.0f);
    float var  = q * (1.0f/512.0f) - mean*mean;
    float inv  = rsqrtf(var + 1e-5f);
    float4 g = *reinterpret_cast<const float4*>(gamma + tid*4);
    float4 bb = *reinterpret_cast<const float4*>(beta + tid*4);
    float4 o4;
    o4.x = (v.x-mean)*inv*g.x + bb.x;
    o4.y = (v.y-mean)*inv*g.y + bb.y;
    o4.z = (v.z-mean)*inv*g.z + bb.z;
    o4.w = (v.w-mean)*inv*g.w + bb.w;
    *reinterpret_cast<float4*>(out + (size_t)row*512 + tid*4) = o4;
}

// -------- launch: fork/join so scale overlaps fc-gemm + ln --------
extern "C" void kernel_launch(void* const* d_in, const int* in_sizes, int n_in,
                              void* d_out, int out_size)
{
    const float* inQ  = (const float*)d_in[0];
    const float* inK  = (const float*)d_in[1];
    const float* inV  = (const float*)d_in[2];
    const void*  mask = d_in[3];
    const float* WQ   = (const float*)d_in[4];
    const float* WK   = (const float*)d_in[5];
    // d_in[6] = W_V, unused (reference bug: V projected with W_K)
    const float* Wfc  = (const float*)d_in[7];
    const float* gam  = (const float*)d_in[8];
    const float* bet  = (const float*)d_in[9];

    float* out_n = (float*)d_out;
    float* out_a = out_n + NORMED_ELEMS;

    float *pQ, *pK, *pV, *pC;
    cudaGetSymbolAddress((void**)&pQ, g_Qp);
    cudaGetSymbolAddress((void**)&pK, g_Kp);
    cudaGetSymbolAddress((void**)&pV, g_Vp);
    cudaGetSymbolAddress((void**)&pC, g_ctx);

    detect_mask_kernel<<<1, 256>>>((const unsigned char*)mask);

    dim3 gg(128, 8);
    gemm_kernel<<<gg, 128>>>(inQ, WQ, nullptr, pQ, 1);   // tf32-rounded outputs
    gemm_kernel<<<gg, 128>>>(inK, WK, nullptr, pK, 1);
    gemm_kernel<<<gg, 128>>>(inV, WK, nullptr, pV, 1);   // W_K: bug preserved

    cudaFuncSetAttribute(attn_kernel, cudaFuncAttributeMaxDynamicSharedMemorySize, ATTN_SMEM);
    attn_kernel<<<dim3(32, NH, BATCH), 128, ATTN_SMEM>>>(mask, out_a);

    // Fork: scale (attn output) runs concurrently with fc-gemm + ln (disjoint buffers).
    cudaStream_t s2;
    cudaEvent_t e_fork, e_join;
    bool forked = (cudaStreamCreateWithFlags(&s2, cudaStreamNonBlocking) == cudaSuccess);
    if (forked &&
        cudaEventCreateWithFlags(&e_fork, cudaEventDisableTiming) == cudaSuccess &&
        cudaEventCreateWithFlags(&e_join, cudaEventDisableTiming) == cudaSuccess &&
        cudaEventRecord(e_fork, 0) == cudaSuccess &&
        cudaStreamWaitEvent(s2, e_fork, 0) == cudaSuccess)
    {
        attn_scale_kernel<<<BATCH*NH*S_LEN, 256, 0, s2>>>(out_a);

        gemm_kernel<<<gg, 128>>>(pC, Wfc, inQ, pQ, 0);   // fc + residual (no rounding)
        ln_kernel<<<BATCH*S_LEN, 128>>>(pQ, gam, bet, out_n);

        cudaEventRecord(e_join, s2);
        cudaStreamWaitEvent(0, e_join, 0);
        cudaEventDestroy(e_fork);
        cudaEventDestroy(e_join);
        cudaStreamDestroy(s2);
    } else {
        if (forked) cudaStreamDestroy(s2);
        attn_scale_kernel<<<BATCH*NH*S_LEN, 256>>>(out_a);
        gemm_kernel<<<gg, 128>>>(pC, Wfc, inQ, pQ, 0);
        ln_kernel<<<BATCH*S_LEN, 128>>>(pQ, gam, bet, out_n);
    }
}

// round 16
// speedup vs baseline: 1.1322x; 1.1322x over previous
#include <cuda_runtime.h>

#define S_LEN 2048
#define DM    512
#define NH    8
#define BATCH 4
#define NORMED_ELEMS (BATCH*S_LEN*DM)
// attn smem: 2x(Ks 32*68 + Vs 32*68) + Es 64*36 = 11008 floats
#define ATTN_SMEM 44032

// -------- scratch --------
__device__ float g_Qp[BATCH*S_LEN*DM];
__device__ float g_Kp[BATCH*S_LEN*DM];
__device__ float g_Vp[BATCH*S_LEN*DM];
__device__ float g_ctx[BATCH*S_LEN*DM];
__device__ float g_rowsum[BATCH*NH*S_LEN];
__device__ int   g_mask_mode;   // 0=int32, 1=uint8/bool, 2=float32

// -------- helpers --------
__device__ __forceinline__ unsigned f2tf(float x){
    unsigned u; asm("cvt.rna.tf32.f32 %0, %1;" : "=r"(u) : "f"(x)); return u;
}
__device__ __forceinline__ float f2tff(float x){ return __uint_as_float(f2tf(x)); }

__device__ __forceinline__ void mma_tf32(float c[4],
    unsigned a0, unsigned a1, unsigned a2, unsigned a3, unsigned b0, unsigned b1)
{
    asm volatile(
      "mma.sync.aligned.m16n8k8.row.col.f32.tf32.tf32.f32 "
      "{%0,%1,%2,%3}, {%4,%5,%6,%7}, {%8,%9}, {%0,%1,%2,%3};"
      : "+f"(c[0]), "+f"(c[1]), "+f"(c[2]), "+f"(c[3])
      : "r"(a0), "r"(a1), "r"(a2), "r"(a3), "r"(b0), "r"(b1));
}

__device__ __forceinline__ void cp16(unsigned dst_smem, const void* src){
    asm volatile("cp.async.cg.shared.global [%0], [%1], 16;"
                 :: "r"(dst_smem), "l"(src) : "memory");
}
__device__ __forceinline__ void cp_commit(){
    asm volatile("cp.async.commit_group;" ::: "memory");
}
__device__ __forceinline__ void cp_wait0(){
    asm volatile("cp.async.wait_group 0;" ::: "memory");
}

// -------- mask dtype probe --------
__global__ void detect_mask_kernel(const unsigned char* __restrict__ m)
{
    __shared__ int s_gt1, s_off;
    if (threadIdx.x == 0){ s_gt1 = 0; s_off = 0; }
    __syncthreads();
    int gt1 = 0, off = 0;
    for (int i = threadIdx.x; i < 8192; i += 256){
        unsigned char v = m[i];
        if (v > 1) gt1 = 1;
        if ((i & 3) && v) off = 1;
    }
    if (gt1) atomicOr(&s_gt1, 1);
    if (off) atomicOr(&s_off, 1);
    __syncthreads();
    if (threadIdx.x == 0) g_mask_mode = s_gt1 ? 2 : (s_off ? 1 : 0);
}

// -------- GEMM with register-prefetch pipeline (R15, unchanged) --------
__global__ void __launch_bounds__(128, 4) gemm_kernel(
    const float* __restrict__ A, const float* __restrict__ W,
    const float* __restrict__ resid, float* __restrict__ C, int round_out)
{
    __shared__ float As[64*36], Ws[64*36];
    const int tid = threadIdx.x, lane = tid & 31, w = tid >> 5;
    const int m0 = blockIdx.x * 64, n0 = blockIdx.y * 64;

    float acc[8][4];
    #pragma unroll
    for (int i = 0; i < 8; i++){ acc[i][0]=0.f; acc[i][1]=0.f; acc[i][2]=0.f; acc[i][3]=0.f; }

    float4 af[4], wf[4];
    #pragma unroll
    for (int i = 0; i < 4; i++){
        int f = tid + i*128, r = f >> 3, fc = (f & 7)*4;
        af[i] = *reinterpret_cast<const float4*>(A + (size_t)(m0+r)*512 + fc);
        wf[i] = *reinterpret_cast<const float4*>(W + (size_t)(n0+r)*512 + fc);
    }

    for (int k0 = 0; k0 < 512; k0 += 32){
        __syncthreads();
        #pragma unroll
        for (int i = 0; i < 4; i++){
            int f = tid + i*128, r = f >> 3, fc = (f & 7)*4;
            As[r*36+fc  ]=f2tff(af[i].x); As[r*36+fc+1]=f2tff(af[i].y);
            As[r*36+fc+2]=f2tff(af[i].z); As[r*36+fc+3]=f2tff(af[i].w);
            Ws[r*36+fc  ]=f2tff(wf[i].x); Ws[r*36+fc+1]=f2tff(wf[i].y);
            Ws[r*36+fc+2]=f2tff(wf[i].z); Ws[r*36+fc+3]=f2tff(wf[i].w);
        }
        if (k0 + 32 < 512){
            #pragma unroll
            for (int i = 0; i < 4; i++){
                int f = tid + i*128, r = f >> 3, fc = (f & 7)*4;
                af[i] = *reinterpret_cast<const float4*>(A + (size_t)(m0+r)*512 + k0+32 + fc);
                wf[i] = *reinterpret_cast<const float4*>(W + (size_t)(n0+r)*512 + k0+32 + fc);
            }
        }
        __syncthreads();
        const int ar = w*16 + (lane >> 2);
        #pragma unroll
        for (int ks = 0; ks < 4; ks++){
            int kk = ks*8 + (lane & 3);
            unsigned a0=__float_as_uint(As[ar*36+kk]),   a1=__float_as_uint(As[(ar+8)*36+kk]);
            unsigned a2=__float_as_uint(As[ar*36+kk+4]), a3=__float_as_uint(As[(ar+8)*36+kk+4]);
            #pragma unroll
            for (int nt = 0; nt < 8; nt++){
                int br = nt*8 + (lane >> 2);
                unsigned b0=__float_as_uint(Ws[br*36+kk]), b1=__float_as_uint(Ws[br*36+kk+4]);
                mma_tf32(acc[nt], a0,a1,a2,a3, b0,b1);
            }
        }
    }

    const int r0 = m0 + w*16 + (lane >> 2);
    const int r1 = r0 + 8;
    #pragma unroll
    for (int nt = 0; nt < 8; nt++){
        int c = n0 + nt*8 + (lane & 3)*2;
        float2 v0 = make_float2(acc[nt][0], acc[nt][1]);
        float2 v1 = make_float2(acc[nt][2], acc[nt][3]);
        if (resid){
            float2 rlo = *reinterpret_cast<const float2*>(resid + (size_t)r0*512 + c);
            float2 rhi = *reinterpret_cast<const float2*>(resid + (size_t)r1*512 + c);
            v0.x += rlo.x; v0.y += rlo.y; v1.x += rhi.x; v1.y += rhi.y;
        }
        if (round_out){
            v0.x = f2tff(v0.x); v0.y = f2tff(v0.y);
            v1.x = f2tff(v1.x); v1.y = f2tff(v1.y);
        }
        *reinterpret_cast<float2*>(C + (size_t)r0*512 + c) = v0;
        *reinterpret_cast<float2*>(C + (size_t)r1*512 + c) = v1;
    }
}

// -------- attention v3: cp.async double-buffered K/V, 1 barrier/tile --------
// q-tile 64, kv-tile 32, 128 threads, grid (32, NH, B).
// Q fragments in registers; mask via register bitmask + shfl; rowsums in regs.
// All arithmetic bit-identical to the R15 kernel.
__global__ void __launch_bounds__(128, 4) attn_kernel(
    const void* __restrict__ maskp, float* __restrict__ attn_out)
{
    extern __shared__ float sm[];
    // [0]=Ks0 [2176]=Vs0 [4352]=Ks1 [6528]=Vs1 [8704]=Es(64*36)
    float* Es = sm + 8704;

    const int tid = threadIdx.x, lane = tid & 31, w = tid >> 5;
    const int la3 = lane & 3, lg = lane >> 2;
    const int b = blockIdx.z, h = blockIdx.y, q0 = blockIdx.x * 64;
    const int mode = g_mask_mode;
    const unsigned char* m8  = (const unsigned char*)maskp;
    const int*           m32 = (const int*)maskp;
    const float*         mf  = (const float*)maskp;
    const size_t mbase = (size_t)b * S_LEN * S_LEN;

    const int rlo = w*16 + lg;          // warp-owned q rows (tile-relative)
    const int rhi = rlo + 8;

    // ---- cp.async destination addresses (per loader thread) ----
    const int lr = tid >> 2, lqo = (tid & 3) * 16;    // kv row 0..31, d-col 0/16/32/48
    unsigned smem_u32 = (unsigned)__cvta_generic_to_shared(sm);
    unsigned kdst0 = smem_u32 + (unsigned)((lr*68 + lqo)*4);
    unsigned vdst0 = kdst0 + 2176*4;
    unsigned kdst1 = kdst0 + 4352*4;
    unsigned vdst1 = vdst0 + 4352*4;

    // gmem K/V row base for this thread's kv row (reshape-bug mapping)
    // row skv = k0 + lr:  ((b*2048 + h*256 + skv/8)*512 + (skv%8)*64
    // prologue: tile 0
    {
        int skv = lr;
        size_t rowoff = ((size_t)(b*S_LEN) + h*256 + (skv>>3))*512 + (size_t)((skv&7)*64 + lqo);
        const float* kp = g_Kp + rowoff;
        const float* vp = g_Vp + rowoff;
        #pragma unroll
        for (int i = 0; i < 4; i++){
            cp16(kdst0 + i*16, kp + i*4);
            cp16(vdst0 + i*16, vp + i*4);
        }
        cp_commit();
    }

    // ---- Q fragments -> registers (tf32-pre-rounded by projection gemm) ----
    unsigned qa[8][4];
    {
        int sq_lo = q0 + rlo, sq_hi = q0 + rhi;
        const float* qlo_p = g_Qp + ((size_t)(b*S_LEN) + h*256 + (sq_lo>>3))*512 + (sq_lo&7)*64;
        const float* qhi_p = g_Qp + ((size_t)(b*S_LEN) + h*256 + (sq_hi>>3))*512 + (sq_hi&7)*64;
        #pragma unroll
        for (int ks = 0; ks < 8; ks++){
            int kk = ks*8 + la3;
            qa[ks][0] = __float_as_uint(qlo_p[kk]);
            qa[ks][1] = __float_as_uint(qhi_p[kk]);
            qa[ks][2] = __float_as_uint(qlo_p[kk+4]);
            qa[ks][3] = __float_as_uint(qhi_p[kk+4]);
        }
    }

    // ---- mask prefetch: lane covers row w*16+(lane>>1), half (lane&1) ----
    const unsigned char* mrow_p = m8 + mbase + (size_t)(q0 + w*16 + (lane>>1))*S_LEN + (lane&1)*16;
    uint4 mreg;
    if (mode == 1) mreg = *reinterpret_cast<const uint4*>(mrow_p);

    float cacc[8][4];
    #pragma unroll
    for (int i = 0; i < 8; i++){ cacc[i][0]=0.f; cacc[i][1]=0.f; cacc[i][2]=0.f; cacc[i][3]=0.f; }
    float rsum_lo = 0.f, rsum_hi = 0.f;

    for (int kt = 0; kt < 64; ++kt){
        const int k0 = kt * 32;
        const int cur = kt & 1;
        const float* Kc = sm + cur*4352;
        const float* Vc = Kc + 2176;

        cp_wait0();        // tile kt data landed in buf[cur]
        __syncthreads();   // visible to all; also: compute(kt-1) done -> buf[1-cur] free

        // ---- issue cp.async for tile kt+1 into the other buffer ----
        if (kt + 1 < 64){
            int skv = k0 + 32 + lr;
            size_t rowoff = ((size_t)(b*S_LEN) + h*256 + (skv>>3))*512 + (size_t)((skv&7)*64 + lqo);
            const float* kp = g_Kp + rowoff;
            const float* vp = g_Vp + rowoff;
            unsigned kd = cur ? kdst0 : kdst1;
            unsigned vd = cur ? vdst0 : vdst1;
            #pragma unroll
            for (int i = 0; i < 4; i++){
                cp16(kd + i*16, kp + i*4);
                cp16(vd + i*16, vp + i*4);
            }
            cp_commit();
        }

        // ---- current tile's mask bits -> per-row 32-bit masks via shfl ----
        unsigned f16 = 0;
        if (mode == 1){
            unsigned x;
            x = mreg.x; f16 |= ((x&1u) | ((x>>7)&2u) | ((x>>14)&4u) | ((x>>21)&8u));
            x = mreg.y; f16 |= ((x&1u) | ((x>>7)&2u) | ((x>>14)&4u) | ((x>>21)&8u)) << 4;
            x = mreg.z; f16 |= ((x&1u) | ((x>>7)&2u) | ((x>>14)&4u) | ((x>>21)&8u)) << 8;
            x = mreg.w; f16 |= ((x&1u) | ((x>>7)&2u) | ((x>>14)&4u) | ((x>>21)&8u)) << 12;
            if (kt + 1 < 64) mreg = *reinterpret_cast<const uint4*>(mrow_p + (kt+1)*32);
        } else {
            int r = q0 + w*16 + (lane>>1);
            int cb = k0 + (lane&1)*16;
            if (mode == 0){
                const int* mp = m32 + mbase + (size_t)r*S_LEN + cb;
                for (int c = 0; c < 16; c++) f16 |= (mp[c] != 0 ? 1u : 0u) << c;
            } else {
                const float* mp = mf + mbase + (size_t)r*S_LEN + cb;
                for (int c = 0; c < 16; c++) f16 |= (mp[c] != 0.f ? 1u : 0u) << c;
            }
        }
        unsigned other = __shfl_xor_sync(0xffffffffu, f16, 1);
        unsigned mrow32 = (lane & 1) ? (other | (f16 << 16)) : (f16 | (other << 16));
        unsigned mlo = __shfl_sync(0xffffffffu, mrow32, lg*2);
        unsigned mhi = __shfl_sync(0xffffffffu, mrow32, lg*2 + 16);

        // ---- scores = Q @ K^T (A from regs, B from Ks buf) ----
        float sc[4][4];
        #pragma unroll
        for (int i = 0; i < 4; i++){ sc[i][0]=0.f; sc[i][1]=0.f; sc[i][2]=0.f; sc[i][3]=0.f; }
        #pragma unroll
        for (int ks = 0; ks < 8; ks++){
            int kk = ks*8 + la3;
            #pragma unroll
            for (int nt = 0; nt < 4; nt++){
                int br = nt*8 + lg;
                unsigned b0 = __float_as_uint(Kc[br*68 + kk]);
                unsigned b1 = __float_as_uint(Kc[br*68 + kk + 4]);
                mma_tf32(sc[nt], qa[ks][0], qa[ks][1], qa[ks][2], qa[ks][3], b0, b1);
            }
        }

        // ---- mask + exp + rowsums (register accumulation, same order) ----
        float plo = 0.f, phi = 0.f;
        #pragma unroll
        for (int nt = 0; nt < 4; nt++){
            int c = nt*8 + la3*2;
            float p0 = ((mlo>>c)&1u)     ? 0.f : __expf(sc[nt][0]*0.125f);
            float p1 = ((mlo>>(c+1))&1u) ? 0.f : __expf(sc[nt][1]*0.125f);
            float p2 = ((mhi>>c)&1u)     ? 0.f : __expf(sc[nt][2]*0.125f);
            float p3 = ((mhi>>(c+1))&1u) ? 0.f : __expf(sc[nt][3]*0.125f);
            Es[rlo*36 + c] = p0; Es[rlo*36 + c+1] = p1;
            Es[rhi*36 + c] = p2; Es[rhi*36 + c+1] = p3;
            plo += p0 + p1; phi += p2 + p3;
        }
        plo += __shfl_xor_sync(0xffffffffu, plo, 1);
        plo += __shfl_xor_sync(0xffffffffu, plo, 2);
        phi += __shfl_xor_sync(0xffffffffu, phi, 1);
        phi += __shfl_xor_sync(0xffffffffu, phi, 2);
        rsum_lo += plo; rsum_hi += phi;
        __syncwarp();   // Es visible within warp (warp-local rows)

        // ---- write unnormalized probs (warp-owned rows) ----
        {
            float* arow = attn_out + ((size_t)(b*NH + h)*S_LEN + q0)*S_LEN + k0;
            #pragma unroll
            for (int ps = 0; ps < 4; ps++){
                int r  = w*16 + ps*4 + (lane >> 3);
                int cc = (lane & 7) * 4;
                float4 v;
                v.x = Es[r*36+cc]; v.y = Es[r*36+cc+1]; v.z = Es[r*36+cc+2]; v.w = Es[r*36+cc+3];
                *reinterpret_cast<float4*>(arow + (size_t)r*S_LEN + cc) = v;
            }
        }
        // ---- context += E @ V (B read transposed from row-major Vs) ----
        #pragma unroll
        for (int ks = 0; ks < 4; ks++){
            int kk = ks*8 + la3;
            unsigned a0 = f2tf(Es[rlo*36 + kk]);
            unsigned a1 = f2tf(Es[rhi*36 + kk]);
            unsigned a2 = f2tf(Es[rlo*36 + kk + 4]);
            unsigned a3 = f2tf(Es[rhi*36 + kk + 4]);
            #pragma unroll
            for (int nt = 0; nt < 8; nt++){
                int br = nt*8 + lg;
                unsigned b0 = __float_as_uint(Vc[kk*68 + br]);       // V[kv=kk][d=br]
                unsigned b1 = __float_as_uint(Vc[(kk+4)*68 + br]);   // V[kv=kk+4][d=br]
                mma_tf32(cacc[nt], a0,a1,a2,a3, b0,b1);
            }
        }
    }

    // ---- normalized context -> g_ctx (b, s, h*64+d) ----
    const float il0 = 1.0f / rsum_lo;
    const float il1 = 1.0f / rsum_hi;
    float* c0p = g_ctx + ((size_t)(b*S_LEN) + q0 + rlo)*512 + h*64;
    float* c1p = g_ctx + ((size_t)(b*S_LEN) + q0 + rhi)*512 + h*64;
    #pragma unroll
    for (int nt = 0; nt < 8; nt++){
        int c = nt*8 + la3*2;
        *reinterpret_cast<float2*>(c0p + c) = make_float2(cacc[nt][0]*il0, cacc[nt][1]*il0);
        *reinterpret_cast<float2*>(c1p + c) = make_float2(cacc[nt][2]*il1, cacc[nt][3]*il1);
    }
    if (la3 == 0){
        size_t base = (size_t)(b*NH + h)*S_LEN + q0;
        g_rowsum[base + rlo] = rsum_lo;
        g_rowsum[base + rhi] = rsum_hi;
    }
}

// -------- rescale attn rows by 1/rowsum (streaming RMW) --------
__global__ void __launch_bounds__(256) attn_scale_kernel(float* __restrict__ attn)
{
    size_t row = blockIdx.x;
    float inv = 1.0f / g_rowsum[row];
    float* p = attn + row * S_LEN;
    int t = threadIdx.x;
    #pragma unroll
    for (int i = 0; i < 2; i++){
        float4 v = *reinterpret_cast<float4*>(p + t*4 + i*1024);
        v.x *= inv; v.y *= inv; v.z *= inv; v.w *= inv;
        *reinterpret_cast<float4*>(p + t*4 + i*1024) = v;
    }
}

// -------- LayerNorm --------
__global__ void __launch_bounds__(128) ln_kernel(
    const float* __restrict__ x, const float* __restrict__ gamma,
    const float* __restrict__ beta, float* __restrict__ out)
{
    __shared__ float rs[4], rq[4];
    int row = blockIdx.x, tid = threadIdx.x;
    const float* xr = x + (size_t)row * 512;
    float4 v = *reinterpret_cast<const float4*>(xr + tid*4);
    float s = v.x + v.y + v.z + v.w;
    float q = v.x*v.x + v.y*v.y + v.z*v.z + v.w*v.w;
    #pragma unroll
    for (int o = 16; o; o >>= 1){
        s += __shfl_xor_sync(0xffffffffu, s, o);
        q += __shfl_xor_sync(0xffffffffu, q, o);
    }
    if ((tid & 31) == 0){ rs[tid>>5] = s; rq[tid>>5] = q; }
    __syncthreads();
    s = rs[0]+rs[1]+rs[2]+rs[3];
    q = rq[0]+rq[1]+rq[2]+rq[3];
    float mean = s * (1.0f/512.0f);
    float var  = q * (1.0f/512.0f) - mean*mean;
    float inv  = rsqrtf(var + 1e-5f);
    float4 g = *reinterpret_cast<const float4*>(gamma + tid*4);
    float4 bb = *reinterpret_cast<const float4*>(beta + tid*4);
    float4 o4;
    o4.x = (v.x-mean)*inv*g.x + bb.x;
    o4.y = (v.y-mean)*inv*g.y + bb.y;
    o4.z = (v.z-mean)*inv*g.z + bb.z;
    o4.w = (v.w-mean)*inv*g.w + bb.w;
    *reinterpret_cast<float4*>(out + (size_t)row*512 + tid*4) = o4;
}

// -------- launch: fork/join so scale overlaps fc-gemm + ln --------
extern "C" void kernel_launch(void* const* d_in, const int* in_sizes, int n_in,
                              void* d_out, int out_size)
{
    const float* inQ  = (const float*)d_in[0];
    const float* inK  = (const float*)d_in[1];
    const float* inV  = (const float*)d_in[2];
    const void*  mask = d_in[3];
    const float* WQ   = (const float*)d_in[4];
    const float* WK   = (const float*)d_in[5];
    // d_in[6] = W_V, unused (reference bug: V projected with W_K)
    const float* Wfc  = (const float*)d_in[7];
    const float* gam  = (const float*)d_in[8];
    const float* bet  = (const float*)d_in[9];

    float* out_n = (float*)d_out;
    float* out_a = out_n + NORMED_ELEMS;

    float *pQ, *pK, *pV, *pC;
    cudaGetSymbolAddress((void**)&pQ, g_Qp);
    cudaGetSymbolAddress((void**)&pK, g_Kp);
    cudaGetSymbolAddress((void**)&pV, g_Vp);
    cudaGetSymbolAddress((void**)&pC, g_ctx);

    detect_mask_kernel<<<1, 256>>>((const unsigned char*)mask);

    dim3 gg(128, 8);
    gemm_kernel<<<gg, 128>>>(inQ, WQ, nullptr, pQ, 1);   // tf32-rounded outputs
    gemm_kernel<<<gg, 128>>>(inK, WK, nullptr, pK, 1);
    gemm_kernel<<<gg, 128>>>(inV, WK, nullptr, pV, 1);   // W_K: bug preserved

    cudaFuncSetAttribute(attn_kernel, cudaFuncAttributeMaxDynamicSharedMemorySize, ATTN_SMEM);
    attn_kernel<<<dim3(32, NH, BATCH), 128, ATTN_SMEM>>>(mask, out_a);

    // Fork: scale (attn output) runs concurrently with fc-gemm + ln (disjoint buffers).
    cudaStream_t s2;
    cudaEvent_t e_fork, e_join;
    bool forked = (cudaStreamCreateWithFlags(&s2, cudaStreamNonBlocking) == cudaSuccess);
    if (forked &&
        cudaEventCreateWithFlags(&e_fork, cudaEventDisableTiming) == cudaSuccess &&
        cudaEventCreateWithFlags(&e_join, cudaEventDisableTiming) == cudaSuccess &&
        cudaEventRecord(e_fork, 0) == cudaSuccess &&
        cudaStreamWaitEvent(s2, e_fork, 0) == cudaSuccess)
    {
        attn_scale_kernel<<<BATCH*NH*S_LEN, 256, 0, s2>>>(out_a);

        gemm_kernel<<<gg, 128>>>(pC, Wfc, inQ, pQ, 0);   // fc + residual (no rounding)
        ln_kernel<<<BATCH*S_LEN, 128>>>(pQ, gam, bet, out_n);

        cudaEventRecord(e_join, s2);
        cudaStreamWaitEvent(0, e_join, 0);
        cudaEventDestroy(e_fork);
        cudaEventDestroy(e_join);
        cudaStreamDestroy(s2);
    } else {
        if (forked) cudaStreamDestroy(s2);
        attn_scale_kernel<<<BATCH*NH*S_LEN, 256>>>(out_a);
        gemm_kernel<<<gg, 128>>>(pC, Wfc, inQ, pQ, 0);
        ln_kernel<<<BATCH*S_LEN, 128>>>(pQ, gam, bet, out_n);
    }
}